// round 5
// baseline (speedup 1.0000x reference)
#include <cuda_runtime.h>
#include <cstdint>

// ---------------------------------------------------------------------------
// NeuralSDEQModel: 65536 paths x 512 steps.
// Strategy:
//   Kernel 1 (build_table): lambda(log_v, t_n) depends only on a scalar log_v
//     (clipped to [-7,2]) and the step index. Tabulate it as 512 rows of
//     256-interval cubic Hermite coefficient float4s using the ANALYTIC MLP
//     derivative. Error ~ O(dx^4) -> negligible vs 1e-3 tolerance.
//   Kernel 2 (sim): DRAM-bound path simulation. Shared-memory tiled transpose
//     so all global loads/stores are coalesced despite path-major (P,S) layout
//     with a time-marching per-thread loop.
// ---------------------------------------------------------------------------

#define N_PATHS 65536
#define N_STEPS 512
#define NTAB 256            // intervals per step row

__device__ float4 g_table[N_STEPS * NTAB];   // cubic coeffs (c0,c1,c2,c3)

// constants (match reference, fp32)
#define DT_F        0.003968253968253968f
#define SQRT_DT_F   0.06299407883487120f
#define KAPPA_F     2.72f
#define THETA_F     (-3.5f)
#define SIGMA_P_F   0.85f
#define RHO_F       (-0.85f)
#define CROSS_F     0.033184430f          // sqrt(1-rho^2)*sqrt_dt = 0.52678269*0.0629940788
#define R_F         0.0373f
#define LAMBDA_MAX_F 3.0f
#define LOG_V_MIN_F (-7.0f)
#define LOG_V_MAX_F 2.0f
#define HSTEP_F     (9.0f / 256.0f)       // table spacing
#define INV_H_F     (256.0f / 9.0f)

// tanh-approx gelu, value + derivative (matches jax.nn.gelu approximate=True)
__device__ __forceinline__ void gelu_vg(float x, float& g, float& dg) {
    const float k0 = 0.7978845608028654f;   // sqrt(2/pi)
    const float k1 = 0.044715f;
    float x2 = x * x;
    float inner = k0 * (x + k1 * x * x2);
    float T = tanhf(inner);
    g  = 0.5f * x * (1.0f + T);
    dg = 0.5f * (1.0f + T) + 0.5f * x * (1.0f - T * T) * k0 * (1.0f + 3.0f * k1 * x2);
}

// One block per step n. 257 threads: thread j evaluates MLP value + derivative
// at node log_v = -7 + j*H, then threads 0..255 emit Hermite cubic coeffs.
__global__ void build_table_kernel(const float* __restrict__ W1, const float* __restrict__ b1,
                                   const float* __restrict__ W2, const float* __restrict__ b2,
                                   const float* __restrict__ W3, const float* __restrict__ b3) {
    __shared__ float sW1[64], sb1[32], sW2[1024], sb2[32], sW3[32];
    __shared__ float sb3;
    __shared__ float fval[NTAB + 1], fder[NTAB + 1];

    int tid = threadIdx.x;
    for (int i = tid; i < 64;   i += blockDim.x) sW1[i] = W1[i];
    for (int i = tid; i < 32;   i += blockDim.x) { sb1[i] = b1[i]; sb2[i] = b2[i]; sW3[i] = W3[i]; }
    for (int i = tid; i < 1024; i += blockDim.x) sW2[i] = W2[i];
    if (tid == 0) sb3 = b3[0];
    __syncthreads();

    // t_n = (n*DT) / (512*DT), computed the same way as the reference (fp32)
    float n_dt = (float)blockIdx.x * DT_F;
    float t = n_dt / (512.0f * DT_F);

    float lv = LOG_V_MIN_F + (float)tid * HSTEP_F;

    // layer 1: 2 -> 32
    float h1[32], d1[32];
#pragma unroll
    for (int j = 0; j < 32; j++) {
        float pre = fmaf(sW1[2 * j], lv, fmaf(sW1[2 * j + 1], t, sb1[j]));
        float g, dg;
        gelu_vg(pre, g, dg);
        h1[j] = g;
        d1[j] = dg * sW1[2 * j];   // d pre / d log_v = W1[j][0]
    }

    // layer 2 (32->32) fused with output layer (32->1)
    float raw = sb3, draw = 0.0f;
    for (int k = 0; k < 32; k++) {
        float pre = sb2[k], dpre = 0.0f;
#pragma unroll
        for (int j = 0; j < 32; j++) {
            float w = sW2[k * 32 + j];
            pre  = fmaf(w, h1[j], pre);
            dpre = fmaf(w, d1[j], dpre);
        }
        float g, dg;
        gelu_vg(pre, g, dg);
        raw  = fmaf(sW3[k], g, raw);
        draw = fmaf(sW3[k], dg * dpre, draw);
    }

    float T = tanhf(raw);
    fval[tid] = LAMBDA_MAX_F * T;
    fder[tid] = LAMBDA_MAX_F * (1.0f - T * T) * draw;
    __syncthreads();

    if (tid < NTAB) {
        float f0 = fval[tid], f1 = fval[tid + 1];
        float m0 = fder[tid] * HSTEP_F, m1 = fder[tid + 1] * HSTEP_F;
        float4 c;
        c.x = f0;
        c.y = m0;
        c.z = 3.0f * (f1 - f0) - 2.0f * m0 - m1;
        c.w = 2.0f * (f0 - f1) + m0 + m1;
        g_table[blockIdx.x * NTAB + tid] = c;
    }
}

// ---------------------------------------------------------------------------
// Simulation kernel: 256 threads/block, each thread owns one path.
// Time processed in 16-step chunks with smem transpose so global traffic is
// coalesced. z tiles are overwritten in place by output tiles.
// ---------------------------------------------------------------------------
#define TB 256    // threads per block (= paths per block)
#define CH 16     // steps per chunk

__global__ void __launch_bounds__(TB) sim_kernel(
    const float* __restrict__ z1, const float* __restrict__ z2,
    const float* __restrict__ init_log_v,
    float* __restrict__ out_lv, float* __restrict__ out_sp, float* __restrict__ out_lsq) {

    __shared__ float s1[CH][TB + 1];
    __shared__ float s2[CH][TB + 1];

    int tid = threadIdx.x;
    int pbase = blockIdx.x * TB;

    float lv  = __ldg(init_log_v);
    float ls  = 0.0f;
    float lsq = 0.0f;

    for (int ch = 0; ch < N_STEPS / CH; ch++) {
        int c0 = ch * CH;

        // --- coalesced load of z1/z2 tile (256 paths x 16 steps) ---
#pragma unroll
        for (int r = 0; r < CH; r++) {
            int idx = r * TB + tid;           // 0..4095
            int s  = idx & (CH - 1);
            int pl = idx >> 4;                // 0..255
            int g  = (pbase + pl) * N_STEPS + c0 + s;
            s1[s][pl] = z1[g];
            s2[s][pl] = z2[g];
        }
        __syncthreads();

        // --- simulate CH steps ---
#pragma unroll
        for (int s = 0; s < CH; s++) {
            int n = c0 + s;
            float z1v = s1[s][tid];
            float z2v = s2[s][tid];

            float dwv = SQRT_DT_F * z1v;
            float dws = fmaf(RHO_F, dwv, CROSS_F * z2v);

            // lambda via cubic Hermite table (lv guaranteed in [-7,2])
            float u = (lv - LOG_V_MIN_F) * INV_H_F;
            int   i = min((int)u, NTAB - 1);
            float fr = u - (float)i;
            float4 cc = __ldg(&g_table[n * NTAB + i]);
            float lam = fmaf(fmaf(fmaf(cc.w, fr, cc.z), fr, cc.y), fr, cc.x);

            // vol = sqrt(max(exp(lv),1e-10)) == exp(0.5*lv) since lv >= -7
            float vol = __expf(0.5f * lv);
            float ev  = vol * vol;

            float mu  = (KAPPA_F * DT_F) * (THETA_F - lv);
            float lvn = lv + mu - lam * (SIGMA_P_F * DT_F) + SIGMA_P_F * dwv;
            lvn = fminf(fmaxf(lvn, LOG_V_MIN_F), LOG_V_MAX_F);

            ls  = ls + (R_F - 0.5f * ev) * DT_F + vol * dws;
            lsq = fmaf(lam * lam, DT_F, lsq);
            lv  = lvn;

            s1[s][tid] = lvn;          // overwrite z tile with outputs
            s2[s][tid] = __expf(ls);
        }
        __syncthreads();

        // --- coalesced store of output tile ---
#pragma unroll
        for (int r = 0; r < CH; r++) {
            int idx = r * TB + tid;
            int s  = idx & (CH - 1);
            int pl = idx >> 4;
            int g  = (pbase + pl) * N_STEPS + c0 + s;
            out_lv[g] = s1[s][pl];
            out_sp[g] = s2[s][pl];
        }
        __syncthreads();
    }

    out_lsq[pbase + tid] = lsq;
}

extern "C" void kernel_launch(void* const* d_in, const int* in_sizes, int n_in,
                              void* d_out, int out_size) {
    const float* z1 = (const float*)d_in[0];
    const float* z2 = (const float*)d_in[1];
    const float* W1 = (const float*)d_in[2];
    const float* b1 = (const float*)d_in[3];
    const float* W2 = (const float*)d_in[4];
    const float* b2 = (const float*)d_in[5];
    const float* W3 = (const float*)d_in[6];
    const float* b3 = (const float*)d_in[7];
    const float* init_log_v = (const float*)d_in[8];

    float* out = (float*)d_out;
    float* out_lv  = out;                                 // (P, S)
    float* out_sp  = out + (size_t)N_PATHS * N_STEPS;     // (P, S)
    float* out_lsq = out + 2ull * N_PATHS * N_STEPS;      // (P,)

    build_table_kernel<<<N_STEPS, NTAB + 1>>>(W1, b1, W2, b2, W3, b3);
    sim_kernel<<<N_PATHS / TB, TB>>>(z1, z2, init_log_v, out_lv, out_sp, out_lsq);
}

// round 7
// speedup vs baseline: 1.2770x; 1.2770x over previous
#include <cuda_runtime.h>
#include <cstdint>

// ---------------------------------------------------------------------------
// NeuralSDEQModel: 65536 paths x 512 steps.
//   Kernel 1 (build_table): tabulate lambda(log_v, t_n) as 512 rows of
//     128-interval cubic Hermite float4 coeffs (analytic MLP derivative).
//     Error ~ h^4/384 * f'''' ~ 1e-6 -> negligible vs 1e-3 tolerance.
//   Kernel 2 (sim): latency-optimized path simulation. Per 16-step chunk the
//     block cooperatively stages BOTH the z tiles AND the 16 table rows into
//     shared memory, so the per-step dependent chain hits LDS (~30 cyc)
//     instead of L2 (~250 cyc). All global traffic is 128-bit coalesced.
// ---------------------------------------------------------------------------

#define N_PATHS 65536
#define N_STEPS 512
#define NTAB 128            // intervals per step row (cubic -> plenty)

__device__ float4 g_table[N_STEPS * NTAB];   // cubic coeffs (c0,c1,c2,c3)

// constants (match reference, fp32)
#define DT_F        0.003968253968253968f
#define SQRT_DT_F   0.06299407883487120f
#define KAPPA_F     2.72f
#define THETA_F     (-3.5f)
#define SIGMA_P_F   0.85f
#define RHO_F       (-0.85f)
#define CROSS_F     0.033184430f          // sqrt(1-rho^2)*sqrt_dt
#define R_F         0.0373f
#define LAMBDA_MAX_F 3.0f
#define LOG_V_MIN_F (-7.0f)
#define LOG_V_MAX_F 2.0f
#define HSTEP_F     (9.0f / 128.0f)       // table spacing
#define INV_H_F     (128.0f / 9.0f)

// tanh-approx gelu, value + derivative (matches jax.nn.gelu approximate=True)
__device__ __forceinline__ void gelu_vg(float x, float& g, float& dg) {
    const float k0 = 0.7978845608028654f;   // sqrt(2/pi)
    const float k1 = 0.044715f;
    float x2 = x * x;
    float inner = k0 * (x + k1 * x * x2);
    float T = tanhf(inner);
    g  = 0.5f * x * (1.0f + T);
    dg = 0.5f * (1.0f + T) + 0.5f * x * (1.0f - T * T) * k0 * (1.0f + 3.0f * k1 * x2);
}

// One block per step n. NTAB+1 threads: thread j evaluates MLP value+derivative
// at node log_v = -7 + j*H, then threads 0..NTAB-1 emit Hermite cubic coeffs.
__global__ void build_table_kernel(const float* __restrict__ W1, const float* __restrict__ b1,
                                   const float* __restrict__ W2, const float* __restrict__ b2,
                                   const float* __restrict__ W3, const float* __restrict__ b3) {
    __shared__ float sW1[64], sb1[32], sW2[1024], sb2[32], sW3[32];
    __shared__ float sb3;
    __shared__ float fval[NTAB + 1], fder[NTAB + 1];

    int tid = threadIdx.x;
    for (int i = tid; i < 64;   i += blockDim.x) sW1[i] = W1[i];
    for (int i = tid; i < 32;   i += blockDim.x) { sb1[i] = b1[i]; sb2[i] = b2[i]; sW3[i] = W3[i]; }
    for (int i = tid; i < 1024; i += blockDim.x) sW2[i] = W2[i];
    if (tid == 0) sb3 = b3[0];
    __syncthreads();

    float n_dt = (float)blockIdx.x * DT_F;
    float t = n_dt / (512.0f * DT_F);

    float lv = LOG_V_MIN_F + (float)tid * HSTEP_F;

    // layer 1: 2 -> 32
    float h1[32], d1[32];
#pragma unroll
    for (int j = 0; j < 32; j++) {
        float pre = fmaf(sW1[2 * j], lv, fmaf(sW1[2 * j + 1], t, sb1[j]));
        float g, dg;
        gelu_vg(pre, g, dg);
        h1[j] = g;
        d1[j] = dg * sW1[2 * j];
    }

    // layer 2 (32->32) fused with output layer (32->1)
    float raw = sb3, draw = 0.0f;
    for (int k = 0; k < 32; k++) {
        float pre = sb2[k], dpre = 0.0f;
#pragma unroll
        for (int j = 0; j < 32; j++) {
            float w = sW2[k * 32 + j];
            pre  = fmaf(w, h1[j], pre);
            dpre = fmaf(w, d1[j], dpre);
        }
        float g, dg;
        gelu_vg(pre, g, dg);
        raw  = fmaf(sW3[k], g, raw);
        draw = fmaf(sW3[k], dg * dpre, draw);
    }

    float T = tanhf(raw);
    fval[tid] = LAMBDA_MAX_F * T;
    fder[tid] = LAMBDA_MAX_F * (1.0f - T * T) * draw;
    __syncthreads();

    if (tid < NTAB) {
        float f0 = fval[tid], f1 = fval[tid + 1];
        float m0 = fder[tid] * HSTEP_F, m1 = fder[tid + 1] * HSTEP_F;
        float4 c;
        c.x = f0;
        c.y = m0;
        c.z = 3.0f * (f1 - f0) - 2.0f * m0 - m1;
        c.w = 2.0f * (f0 - f1) + m0 + m1;
        g_table[blockIdx.x * NTAB + tid] = c;
    }
}

// ---------------------------------------------------------------------------
// Simulation kernel: 128 threads/block (1 path/thread) -> 512 blocks for
// better wave balance. Per 16-step chunk: stage z tiles + 16 table rows in
// smem, simulate, write outputs back through smem, store vectorized.
// ---------------------------------------------------------------------------
#define TB 128    // threads per block (= paths per block)
#define CH 16     // steps per chunk

__global__ void __launch_bounds__(TB, 4) sim_kernel(
    const float* __restrict__ z1, const float* __restrict__ z2,
    const float* __restrict__ init_log_v,
    float* __restrict__ out_lv, float* __restrict__ out_sp, float* __restrict__ out_lsq) {

    __shared__ float  s1[CH][TB + 1];
    __shared__ float  s2[CH][TB + 1];
    __shared__ float4 stab[CH * NTAB];     // 16 rows x 128 coeffs = 32 KB

    int tid = threadIdx.x;
    int pbase = blockIdx.x * TB;

    float lv  = __ldg(init_log_v);
    float ls  = 0.0f;
    float lsq = 0.0f;

    for (int ch = 0; ch < N_STEPS / CH; ch++) {
        int c0 = ch * CH;

        // --- coalesced 128-bit loads of z1/z2 tile (TB paths x CH steps) ---
#pragma unroll
        for (int r = 0; r < (TB * CH) / (TB * 4); r++) {   // 4 iters
            int idx = r * TB + tid;          // 0..511 (float4 index)
            int pl  = idx >> 2;              // path lane 0..127
            int s4  = (idx & 3) * 4;         // step sub-offset 0,4,8,12
            size_t g = (size_t)(pbase + pl) * N_STEPS + c0 + s4;
            float4 a = *(const float4*)(z1 + g);
            float4 b = *(const float4*)(z2 + g);
            s1[s4 + 0][pl] = a.x; s1[s4 + 1][pl] = a.y; s1[s4 + 2][pl] = a.z; s1[s4 + 3][pl] = a.w;
            s2[s4 + 0][pl] = b.x; s2[s4 + 1][pl] = b.y; s2[s4 + 2][pl] = b.z; s2[s4 + 3][pl] = b.w;
        }

        // --- stage this chunk's 16 table rows (contiguous) into smem ---
#pragma unroll
        for (int r = 0; r < (CH * NTAB) / TB; r++) {       // 16 iters
            int i = r * TB + tid;
            stab[i] = g_table[c0 * NTAB + i];
        }
        __syncthreads();

        // --- simulate CH steps ---
#pragma unroll
        for (int s = 0; s < CH; s++) {
            float z1v = s1[s][tid];
            float z2v = s2[s][tid];

            float dwv = SQRT_DT_F * z1v;
            float dws = fmaf(RHO_F, dwv, CROSS_F * z2v);

            // lambda via cubic Hermite table in smem (lv in [-7,2] always)
            float u = (lv - LOG_V_MIN_F) * INV_H_F;
            int   i = min((int)u, NTAB - 1);
            float fr = u - (float)i;
            float4 cc = stab[s * NTAB + i];
            float lam = fmaf(fmaf(fmaf(cc.w, fr, cc.z), fr, cc.y), fr, cc.x);

            // vol = sqrt(max(exp(lv),1e-10)) == exp(0.5*lv) since lv >= -7
            float vol = __expf(0.5f * lv);
            float ev  = vol * vol;

            float mu  = (KAPPA_F * DT_F) * (THETA_F - lv);
            float lvn = lv + mu - lam * (SIGMA_P_F * DT_F) + SIGMA_P_F * dwv;
            lvn = fminf(fmaxf(lvn, LOG_V_MIN_F), LOG_V_MAX_F);

            ls  = ls + (R_F - 0.5f * ev) * DT_F + vol * dws;
            lsq = fmaf(lam * lam, DT_F, lsq);
            lv  = lvn;

            s1[s][tid] = lvn;          // overwrite z tiles with outputs
            s2[s][tid] = __expf(ls);
        }
        __syncthreads();

        // --- coalesced 128-bit stores of output tile ---
#pragma unroll
        for (int r = 0; r < 4; r++) {
            int idx = r * TB + tid;
            int pl  = idx >> 2;
            int s4  = (idx & 3) * 4;
            size_t g = (size_t)(pbase + pl) * N_STEPS + c0 + s4;
            float4 a, b;
            a.x = s1[s4 + 0][pl]; a.y = s1[s4 + 1][pl]; a.z = s1[s4 + 2][pl]; a.w = s1[s4 + 3][pl];
            b.x = s2[s4 + 0][pl]; b.y = s2[s4 + 1][pl]; b.z = s2[s4 + 2][pl]; b.w = s2[s4 + 3][pl];
            *(float4*)(out_lv + g) = a;
            *(float4*)(out_sp + g) = b;
        }
        __syncthreads();
    }

    out_lsq[pbase + tid] = lsq;
}

extern "C" void kernel_launch(void* const* d_in, const int* in_sizes, int n_in,
                              void* d_out, int out_size) {
    const float* z1 = (const float*)d_in[0];
    const float* z2 = (const float*)d_in[1];
    const float* W1 = (const float*)d_in[2];
    const float* b1 = (const float*)d_in[3];
    const float* W2 = (const float*)d_in[4];
    const float* b2 = (const float*)d_in[5];
    const float* W3 = (const float*)d_in[6];
    const float* b3 = (const float*)d_in[7];
    const float* init_log_v = (const float*)d_in[8];

    float* out = (float*)d_out;
    float* out_lv  = out;                                 // (P, S)
    float* out_sp  = out + (size_t)N_PATHS * N_STEPS;     // (P, S)
    float* out_lsq = out + 2ull * N_PATHS * N_STEPS;      // (P,)

    build_table_kernel<<<N_STEPS, NTAB + 1>>>(W1, b1, W2, b2, W3, b3);
    sim_kernel<<<N_PATHS / TB, TB>>>(z1, z2, init_log_v, out_lv, out_sp, out_lsq);
}